// round 2
// baseline (speedup 1.0000x reference)
#include <cuda_runtime.h>

// VQ: B=16, N=4096, D=128, M=2048
// out layout (float32): quantized_st[8388608], loss[1], perp[1], indices[65536]

#define BN_TOTAL 65536
#define M_CB     2048
#define D_DIM    128
#define Q_ELEMS  8388608
#define LOSS_OFF 8388608
#define PERP_OFF 8388609
#define IDX_OFF  8388610

__device__ float g_l2k[M_CB];
__device__ int   g_counts[M_CB];
__device__ float g_loss;

// ---------------------------------------------------------------------------
// prep: ||k||^2 per codebook row (STRICT sequential fp32 mul+add, mimicking
// XLA's scalar reduce lowering), zero counts + loss accumulator
// ---------------------------------------------------------------------------
__global__ void prep_kernel(const float* __restrict__ w) {
    int t = blockIdx.x * blockDim.x + threadIdx.x;
    if (t < M_CB) {
        const float* wr = w + (size_t)t * D_DIM;
        float s = 0.f;
        for (int i = 0; i < D_DIM; i++) {
            float v = __ldg(wr + i);
            s = __fadd_rn(s, __fmul_rn(v, v));   // no fma, no reassociation
        }
        g_l2k[t]    = s;
        g_counts[t] = 0;
    }
    if (t == 0 && blockIdx.x == 0) g_loss = 0.f;
}

// ---------------------------------------------------------------------------
// main: per 64-query block: distance GEMM vs all 2048 codes (fp32),
// fused argmin with reference-identical rounding, gather, quantized_st,
// loss partial, histogram, indices.
// Dynamic smem: qs[128][64] (32KB) + ks[128][64] (32KB) = 64KB.
// ---------------------------------------------------------------------------
__global__ __launch_bounds__(256) void vq_main_kernel(
    const float* __restrict__ x, const float* __restrict__ w,
    float* __restrict__ out)
{
    extern __shared__ float smem[];
    float* qs = smem;              // [k][m] k-major, 128*64
    float* ks = smem + 128 * 64;   // [k][n] k-major, 128*64

    __shared__ float l2q_s[64];
    __shared__ int   best_s[64];
    __shared__ float wsum[8];

    const int tid  = threadIdx.x;
    const int m0   = blockIdx.x * 64;
    const int tx   = tid & 15;        // 16 column-owners
    const int ty   = tid >> 4;        // 16 row-owners
    const int lrow = tid >> 2;        // loader: row 0..63
    const int lkb  = (tid & 3) * 32;  // loader: k-base {0,32,64,96}

    // ---- load x tile, transposed to k-major
    {
        const float4* src = reinterpret_cast<const float4*>(
            x + (size_t)(m0 + lrow) * D_DIM + lkb);
#pragma unroll
        for (int i = 0; i < 8; i++) {
            float4 v = src[i];
            int k = lkb + i * 4;
            qs[(k+0)*64 + lrow] = v.x;
            qs[(k+1)*64 + lrow] = v.y;
            qs[(k+2)*64 + lrow] = v.z;
            qs[(k+3)*64 + lrow] = v.w;
        }
    }
    __syncthreads();

    // ---- l2_q per row: STRICT sequential fp32 mul+add (match reference)
    if (tid < 64) {
        float s = 0.f;
        for (int k = 0; k < D_DIM; k++) {
            float v = qs[k * 64 + tid];
            s = __fadd_rn(s, __fmul_rn(v, v));
        }
        l2q_s[tid] = s;
    }

    float rmin[4];
    int   ridx[4];
#pragma unroll
    for (int i = 0; i < 4; i++) { rmin[i] = 3.0e38f; ridx[i] = 0; }

    for (int nt = 0; nt < M_CB / 64; nt++) {
        const int n0 = nt * 64;
        __syncthreads();   // previous tile's compute done before ks overwrite
        {
            const float4* src = reinterpret_cast<const float4*>(
                w + (size_t)(n0 + lrow) * D_DIM + lkb);
#pragma unroll
            for (int i = 0; i < 8; i++) {
                float4 v = src[i];
                int k = lkb + i * 4;
                ks[(k+0)*64 + lrow] = v.x;
                ks[(k+1)*64 + lrow] = v.y;
                ks[(k+2)*64 + lrow] = v.z;
                ks[(k+3)*64 + lrow] = v.w;
            }
        }
        __syncthreads();

        float acc[4][4];
#pragma unroll
        for (int i = 0; i < 4; i++)
#pragma unroll
            for (int j = 0; j < 4; j++) acc[i][j] = 0.f;

#pragma unroll 8
        for (int kk = 0; kk < 128; kk++) {
            float4 a = *reinterpret_cast<const float4*>(qs + kk * 64 + (ty << 2));
            float4 b = *reinterpret_cast<const float4*>(ks + kk * 64 + (tx << 2));
            acc[0][0] = fmaf(a.x, b.x, acc[0][0]);
            acc[0][1] = fmaf(a.x, b.y, acc[0][1]);
            acc[0][2] = fmaf(a.x, b.z, acc[0][2]);
            acc[0][3] = fmaf(a.x, b.w, acc[0][3]);
            acc[1][0] = fmaf(a.y, b.x, acc[1][0]);
            acc[1][1] = fmaf(a.y, b.y, acc[1][1]);
            acc[1][2] = fmaf(a.y, b.z, acc[1][2]);
            acc[1][3] = fmaf(a.y, b.w, acc[1][3]);
            acc[2][0] = fmaf(a.z, b.x, acc[2][0]);
            acc[2][1] = fmaf(a.z, b.y, acc[2][1]);
            acc[2][2] = fmaf(a.z, b.z, acc[2][2]);
            acc[2][3] = fmaf(a.z, b.w, acc[2][3]);
            acc[3][0] = fmaf(a.w, b.x, acc[3][0]);
            acc[3][1] = fmaf(a.w, b.y, acc[3][1]);
            acc[3][2] = fmaf(a.w, b.z, acc[3][2]);
            acc[3][3] = fmaf(a.w, b.w, acc[3][3]);
        }

        // fused argmin epilogue, REFERENCE ROUNDING:
        //   v = fl( fl(l2q + l2k) - 2*sim )   [fma(-2,s,L) == single-rounded,
        //                                      since 2*s is exact]
#pragma unroll
        for (int j = 0; j < 4; j++) {
            const int n = n0 + (tx << 2) + j;
            const float ln = g_l2k[n];
#pragma unroll
            for (int i = 0; i < 4; i++) {
                const float L = __fadd_rn(l2q_s[(ty << 2) + i], ln);
                const float v = __fmaf_rn(-2.f, acc[i][j], L);
                if (v < rmin[i]) { rmin[i] = v; ridx[i] = n; }  // strict <: first idx wins
            }
        }
    }

    // ---- cross-thread argmin reduction (reuse ks region)
    __syncthreads();
    float* rv  = ks;                                    // [64][17]
    int*   rix = reinterpret_cast<int*>(ks + 64 * 17);  // [64][17]
#pragma unroll
    for (int i = 0; i < 4; i++) {
        int r = (ty << 2) + i;
        rv [r * 17 + tx] = rmin[i];
        rix[r * 17 + tx] = ridx[i];
    }
    __syncthreads();
    if (tid < 64) {
        float bv = rv[tid * 17];
        int   bi = rix[tid * 17];
#pragma unroll
        for (int t2 = 1; t2 < 16; t2++) {
            float v  = rv [tid * 17 + t2];
            int   ix = rix[tid * 17 + t2];
            if (v < bv || (v == bv && ix < bi)) { bv = v; bi = ix; }
        }
        best_s[tid] = bi;
        atomicAdd(&g_counts[bi], 1);
        out[IDX_OFF + m0 + tid] = (float)bi;
    }
    __syncthreads();

    // ---- gather z, write quantized_st = x + (z - x), accumulate loss partial
    const int best = best_s[lrow];
    const float4* wz = reinterpret_cast<const float4*>(
        w + (size_t)best * D_DIM + lkb);
    float4* outq = reinterpret_cast<float4*>(
        out + (size_t)(m0 + lrow) * D_DIM + lkb);
    float lsum = 0.f;
#pragma unroll
    for (int i = 0; i < 8; i++) {
        float4 z = wz[i];
        int k = lkb + i * 4;
        float4 xv;
        xv.x = qs[(k+0)*64 + lrow];
        xv.y = qs[(k+1)*64 + lrow];
        xv.z = qs[(k+2)*64 + lrow];
        xv.w = qs[(k+3)*64 + lrow];
        float4 qv;
        qv.x = __fadd_rn(xv.x, __fsub_rn(z.x, xv.x));
        qv.y = __fadd_rn(xv.y, __fsub_rn(z.y, xv.y));
        qv.z = __fadd_rn(xv.z, __fsub_rn(z.z, xv.z));
        qv.w = __fadd_rn(xv.w, __fsub_rn(z.w, xv.w));
        outq[i] = qv;
        float d0 = __fsub_rn(qv.x, xv.x), d1 = __fsub_rn(qv.y, xv.y);
        float d2 = __fsub_rn(qv.z, xv.z), d3 = __fsub_rn(qv.w, xv.w);
        lsum += d0*d0 + d1*d1 + d2*d2 + d3*d3;
    }
    // block-reduce loss partial
#pragma unroll
    for (int o = 16; o > 0; o >>= 1)
        lsum += __shfl_down_sync(0xffffffffu, lsum, o);
    if ((tid & 31) == 0) wsum[tid >> 5] = lsum;
    __syncthreads();
    if (tid == 0) {
        float s = 0.f;
#pragma unroll
        for (int i2 = 0; i2 < 8; i2++) s += wsum[i2];
        atomicAdd(&g_loss, s);
    }
}

// ---------------------------------------------------------------------------
// finalize: loss mean + perplexity from histogram
// ---------------------------------------------------------------------------
__global__ void finalize_kernel(float* __restrict__ out) {
    int t = threadIdx.x;
    float s = 0.f;
    for (int i = t; i < M_CB; i += 256) {
        float p = (float)g_counts[i] * (1.0f / 65536.0f);
        s += p * logf(p + 1e-10f);
    }
#pragma unroll
    for (int o = 16; o > 0; o >>= 1)
        s += __shfl_down_sync(0xffffffffu, s, o);
    __shared__ float ws[8];
    if ((t & 31) == 0) ws[t >> 5] = s;
    __syncthreads();
    if (t == 0) {
        float tot = 0.f;
#pragma unroll
        for (int i = 0; i < 8; i++) tot += ws[i];
        out[LOSS_OFF] = g_loss * (1.0f / 8388608.0f);
        out[PERP_OFF] = expf(-tot);
    }
}

// ---------------------------------------------------------------------------
extern "C" void kernel_launch(void* const* d_in, const int* in_sizes, int n_in,
                              void* d_out, int out_size) {
    const float* x = (const float*)d_in[0];
    const float* w = (const float*)d_in[1];
    // robustness: identify tensors by size (x: 8388608, weight: 262144)
    if (n_in >= 2 && in_sizes[0] == M_CB * D_DIM && in_sizes[1] == Q_ELEMS) {
        x = (const float*)d_in[1];
        w = (const float*)d_in[0];
    }
    float* out = (float*)d_out;

    // 64KB dynamic smem opt-in (idempotent; persists from first call)
    cudaFuncSetAttribute(vq_main_kernel,
                         cudaFuncAttributeMaxDynamicSharedMemorySize, 65536);

    prep_kernel<<<(M_CB + 255) / 256, 256>>>(w);
    vq_main_kernel<<<BN_TOTAL / 64, 256, 65536>>>(x, w, out);
    finalize_kernel<<<1, 256>>>(out);
}

// round 4
// speedup vs baseline: 1.9912x; 1.9912x over previous
#include <cuda_runtime.h>
#include <cuda_bf16.h>
#include <cstdint>

// VQ: B=16, N=4096, D=128, M=2048
// out layout (float32): quantized_st[8388608], loss[1], perp[1], indices[65536]

#define BN_TOTAL 65536
#define M_CB     2048
#define D_DIM    128
#define Q_ELEMS  8388608
#define LOSS_OFF 8388608
#define PERP_OFF 8388609
#define IDX_OFF  8388610

#define ROW_PITCH   272u                 // 136 bf16 per row (128 data + 8 pad)
#define SPLIT_BYTES (M_CB * ROW_PITCH)   // 557056 per split image
#define A_SPLIT     34816u               // 128 rows * 272
#define B_SPLIT     17408u               // 64 rows * 272
#define B_BUF       52224u               // 3 splits
#define N_TILE      64
#define NUM_NT      32

// SMEM map (bytes)
#define SM_A     0u
#define SM_B     104448u                 // 2 bufs * 52224
#define SM_L2K   208896u
#define SM_L2Q   217088u
#define SM_REDV  217600u
#define SM_REDI  218624u
#define SM_BEST  219648u
#define SM_WSUM  220160u
#define SM_TOTAL 220192u

__device__ float g_l2k[M_CB];
__device__ int   g_counts[M_CB];
__device__ float g_loss;
__device__ __align__(256) unsigned char g_wsplit[3u * SPLIT_BYTES];

// ---------------------------------------------------------------------------
__device__ __forceinline__ uint32_t smem_to_u32(const void* p) {
    uint32_t a;
    asm("{ .reg .u64 t; cvta.to.shared.u64 t, %1; cvt.u32.u64 %0, t; }"
        : "=r"(a) : "l"(p));
    return a;
}
__device__ __forceinline__ void cp16(uint32_t dst, const void* src) {
    asm volatile("cp.async.cg.shared.global [%0], [%1], 16;"
                 :: "r"(dst), "l"(src) : "memory");
}
__device__ __forceinline__ void cp_commit() {
    asm volatile("cp.async.commit_group;" ::: "memory");
}
__device__ __forceinline__ void cp_wait1() {
    asm volatile("cp.async.wait_group 1;" ::: "memory");
}
__device__ __forceinline__ void cp_wait0() {
    asm volatile("cp.async.wait_group 0;" ::: "memory");
}
__device__ __forceinline__ void mma_bf16(float* d, const uint32_t* a, const uint32_t* b) {
    asm volatile(
        "mma.sync.aligned.m16n8k16.row.col.f32.bf16.bf16.f32 "
        "{%0,%1,%2,%3}, {%4,%5,%6,%7}, {%8,%9}, {%0,%1,%2,%3};"
        : "+f"(d[0]), "+f"(d[1]), "+f"(d[2]), "+f"(d[3])
        : "r"(a[0]), "r"(a[1]), "r"(a[2]), "r"(a[3]), "r"(b[0]), "r"(b[1]));
}
__device__ __forceinline__ void split3(float v, __nv_bfloat16& h,
                                       __nv_bfloat16& m, __nv_bfloat16& lo) {
    h = __float2bfloat16_rn(v);
    float r1 = __fsub_rn(v, __bfloat162float(h));
    m = __float2bfloat16_rn(r1);
    float r2 = __fsub_rn(r1, __bfloat162float(m));
    lo = __float2bfloat16_rn(r2);
}

// ---------------------------------------------------------------------------
// prep: codebook 3-way bf16 splits into padded gmem images + ||k||^2 + zeroing
// grid 32 x 256
// ---------------------------------------------------------------------------
__global__ void prep_kernel(const float* __restrict__ w) {
    const int gt = blockIdx.x * 256 + threadIdx.x;    // 0..8191
#pragma unroll
    for (int i = 0; i < 4; i++) {
        int oct = gt * 4 + i;                         // 0..32767
        int n = oct >> 4, k0 = (oct & 15) << 3;
        const float* src = w + (size_t)n * D_DIM + k0;
        __align__(16) __nv_bfloat16 hi[8], mi[8], lo[8];
#pragma unroll
        for (int j = 0; j < 8; j++) split3(src[j], hi[j], mi[j], lo[j]);
        uint32_t off = (uint32_t)n * ROW_PITCH + (uint32_t)k0 * 2;
        *(uint4*)(g_wsplit + off)                   = *(uint4*)hi;
        *(uint4*)(g_wsplit + SPLIT_BYTES + off)     = *(uint4*)mi;
        *(uint4*)(g_wsplit + 2u * SPLIT_BYTES + off) = *(uint4*)lo;
    }
    if (gt < M_CB) {
        const float* wr = w + (size_t)gt * D_DIM;
        float s = 0.f;
        for (int i = 0; i < D_DIM; i++)
            s = __fadd_rn(s, __fmul_rn(wr[i], wr[i]));   // strict sequential
        g_l2k[gt]    = s;
        g_counts[gt] = 0;
        if (gt == 0) g_loss = 0.f;
    }
}

// ---------------------------------------------------------------------------
__device__ __forceinline__ void load_b(uint32_t sb, int buf, int nt, int tid) {
#pragma unroll
    for (int s = 0; s < 3; s++) {
        const unsigned char* src =
            g_wsplit + (size_t)s * SPLIT_BYTES + (size_t)nt * B_SPLIT;
        uint32_t dst = sb + SM_B + (uint32_t)buf * B_BUF + (uint32_t)s * B_SPLIT;
        for (int i = tid; i < (int)(B_SPLIT / 16); i += 256)
            cp16(dst + (uint32_t)i * 16u, src + (size_t)i * 16);
    }
}

// ---------------------------------------------------------------------------
// main: M=128 query tile per CTA; 6-pass split-bf16 HMMA distance GEMM with
// fused argmin; gather/quantized_st/loss/hist epilogue.
// ---------------------------------------------------------------------------
__global__ __launch_bounds__(256, 1)
void vq_main_kernel(const float* __restrict__ x, const float* __restrict__ w,
                    float* __restrict__ out)
{
    extern __shared__ char smem[];
    const uint32_t sb = smem_to_u32(smem);
    const int tid = threadIdx.x;
    const int wid = tid >> 5, l = tid & 31;
    const int wx = wid & 3, wy = wid >> 2;
    const int lq = l >> 2, lr = l & 3;
    const int m0 = blockIdx.x * 128;

    float* l2k_s  = (float*)(smem + SM_L2K);
    float* l2q_s  = (float*)(smem + SM_L2Q);
    float* redv   = (float*)(smem + SM_REDV);
    int*   redi   = (int*)  (smem + SM_REDI);
    int*   best_s = (int*)  (smem + SM_BEST);
    float* wsum   = (float*)(smem + SM_WSUM);

    // ---- build A split images (hi/mid/lo), padded rows
#pragma unroll
    for (int i = 0; i < 8; i++) {
        int idx = tid + (i << 8);               // 0..2047 octets
        int r = idx >> 4, k0 = (idx & 15) << 3;
        const float4* src = (const float4*)(x + (size_t)(m0 + r) * D_DIM + k0);
        float4 v0 = src[0], v1 = src[1];
        float vv[8] = {v0.x, v0.y, v0.z, v0.w, v1.x, v1.y, v1.z, v1.w};
        __align__(16) __nv_bfloat16 hi[8], mi[8], lo[8];
#pragma unroll
        for (int j = 0; j < 8; j++) split3(vv[j], hi[j], mi[j], lo[j]);
        uint32_t off = SM_A + (uint32_t)r * ROW_PITCH + (uint32_t)k0 * 2;
        *(uint4*)(smem + off)                = *(uint4*)hi;
        *(uint4*)(smem + off + A_SPLIT)      = *(uint4*)mi;
        *(uint4*)(smem + off + 2u * A_SPLIT) = *(uint4*)lo;
    }
    // ---- stage l2k
    {
        const float4* src = (const float4*)g_l2k;
        float4* dst = (float4*)l2k_s;
        dst[tid]       = src[tid];
        dst[tid + 256] = src[tid + 256];
    }
    // ---- l2q per row: strict sequential fp32 (reference rounding)
    if (tid < 128) {
        const float* xr = x + (size_t)(m0 + tid) * D_DIM;
        float s = 0.f;
        for (int k = 0; k < D_DIM; k++)
            s = __fadd_rn(s, __fmul_rn(xr[k], xr[k]));
        l2q_s[tid] = s;
    }

    load_b(sb, 0, 0, tid);
    cp_commit();
    __syncthreads();

    float lqr[2][2];
#pragma unroll
    for (int mi = 0; mi < 2; mi++)
#pragma unroll
        for (int h = 0; h < 2; h++)
            lqr[mi][h] = l2q_s[wx * 32 + mi * 16 + h * 8 + lq];

    const uint32_t aBase  = SM_A + (uint32_t)(wx * 32 + lq) * ROW_PITCH + (uint32_t)lr * 4u;
    const uint32_t bBase0 = SM_B + (uint32_t)(wy * 32 + lq) * ROW_PITCH + (uint32_t)lr * 4u;

    float rmin[2][2];
    int   ridx[2][2];
#pragma unroll
    for (int mi = 0; mi < 2; mi++)
#pragma unroll
        for (int h = 0; h < 2; h++) { rmin[mi][h] = 3.0e38f; ridx[mi][h] = 0; }

    for (int nt = 0; nt < NUM_NT; nt++) {
        if (nt + 1 < NUM_NT) {
            load_b(sb, (nt + 1) & 1, nt + 1, tid);
            cp_commit();
            cp_wait1();          // tile nt complete (FIFO)
        } else {
            cp_wait0();
        }
        __syncthreads();

        float acc[2][4][4];
#pragma unroll
        for (int mi = 0; mi < 2; mi++)
#pragma unroll
            for (int ni = 0; ni < 4; ni++)
#pragma unroll
                for (int q = 0; q < 4; q++) acc[mi][ni][q] = 0.f;

        const uint32_t bB = bBase0 + (uint32_t)(nt & 1) * B_BUF;

        for (int c = 0; c < 8; c++) {
            const uint32_t kb = (uint32_t)c * 32u;
            uint32_t aF[3][2][4];
#pragma unroll
            for (int s = 0; s < 3; s++) {
                uint32_t ab = aBase + kb + (uint32_t)s * A_SPLIT;
#pragma unroll
                for (int mi = 0; mi < 2; mi++) {
                    uint32_t r0 = ab + (uint32_t)mi * (16u * ROW_PITCH);
                    aF[s][mi][0] = *(const uint32_t*)(smem + r0);
                    aF[s][mi][1] = *(const uint32_t*)(smem + r0 + 8u * ROW_PITCH);
                    aF[s][mi][2] = *(const uint32_t*)(smem + r0 + 16u);
                    aF[s][mi][3] = *(const uint32_t*)(smem + r0 + 8u * ROW_PITCH + 16u);
                }
            }
            uint32_t bF[3][4][2];
#pragma unroll
            for (int s = 0; s < 3; s++) {
                uint32_t bbs = bB + kb + (uint32_t)s * B_SPLIT;
#pragma unroll
                for (int ni = 0; ni < 4; ni++) {
                    uint32_t r0 = bbs + (uint32_t)ni * (8u * ROW_PITCH);
                    bF[s][ni][0] = *(const uint32_t*)(smem + r0);
                    bF[s][ni][1] = *(const uint32_t*)(smem + r0 + 16u);
                }
            }
            const int PA[6] = {0, 0, 1, 0, 2, 1};
            const int PB[6] = {0, 1, 0, 2, 0, 1};
#pragma unroll
            for (int p = 0; p < 6; p++)
#pragma unroll
                for (int mi = 0; mi < 2; mi++)
#pragma unroll
                    for (int ni = 0; ni < 4; ni++)
                        mma_bf16(acc[mi][ni], aF[PA[p]][mi], bF[PB[p]][ni]);
        }

        // fused argmin epilogue (reference rounding; ascending index order)
#pragma unroll
        for (int mi = 0; mi < 2; mi++)
#pragma unroll
            for (int ni = 0; ni < 4; ni++) {
                const int col0 = nt * 64 + wy * 32 + ni * 8 + (lr << 1);
                const float2 lk = *(const float2*)(l2k_s + col0);
                float v;
                v = __fmaf_rn(-2.f, acc[mi][ni][0], __fadd_rn(lqr[mi][0], lk.x));
                if (v < rmin[mi][0]) { rmin[mi][0] = v; ridx[mi][0] = col0; }
                v = __fmaf_rn(-2.f, acc[mi][ni][1], __fadd_rn(lqr[mi][0], lk.y));
                if (v < rmin[mi][0]) { rmin[mi][0] = v; ridx[mi][0] = col0 + 1; }
                v = __fmaf_rn(-2.f, acc[mi][ni][2], __fadd_rn(lqr[mi][1], lk.x));
                if (v < rmin[mi][1]) { rmin[mi][1] = v; ridx[mi][1] = col0; }
                v = __fmaf_rn(-2.f, acc[mi][ni][3], __fadd_rn(lqr[mi][1], lk.y));
                if (v < rmin[mi][1]) { rmin[mi][1] = v; ridx[mi][1] = col0 + 1; }
            }
        __syncthreads();   // compute done before next iter overwrites this buf
    }

    // ---- cross-lane (4 lanes share a row) then cross-warp (wy) reduction
#pragma unroll
    for (int mi = 0; mi < 2; mi++)
#pragma unroll
        for (int h = 0; h < 2; h++) {
            float v = rmin[mi][h];
            int   ix = ridx[mi][h];
#pragma unroll
            for (int off = 1; off <= 2; off <<= 1) {
                float ov = __shfl_xor_sync(0xffffffffu, v, off);
                int   oi = __shfl_xor_sync(0xffffffffu, ix, off);
                if (ov < v || (ov == v && oi < ix)) { v = ov; ix = oi; }
            }
            if (lr == 0) {
                int row = wx * 32 + mi * 16 + h * 8 + lq;
                redv[row * 2 + wy] = v;
                redi[row * 2 + wy] = ix;
            }
        }
    __syncthreads();
    if (tid < 128) {
        float v0 = redv[tid * 2];     int i0 = redi[tid * 2];
        float v1 = redv[tid * 2 + 1]; int i1 = redi[tid * 2 + 1];
        int best = (v1 < v0 || (v1 == v0 && i1 < i0)) ? i1 : i0;
        best_s[tid] = best;
        atomicAdd(&g_counts[best], 1);
        out[IDX_OFF + m0 + tid] = (float)best;
    }
    __syncthreads();

    // ---- gather z, quantized_st = x + (z - x), loss partial (half-row/thread)
    {
        const int r  = tid >> 1;
        const int kb = (tid & 1) << 6;
        const int best = best_s[r];
        const float4* xr = (const float4*)(x + (size_t)(m0 + r) * D_DIM + kb);
        const float4* wz = (const float4*)(w + (size_t)best * D_DIM + kb);
        float4* oq = (float4*)(out + (size_t)(m0 + r) * D_DIM + kb);
        float lsum = 0.f;
#pragma unroll
        for (int i = 0; i < 16; i++) {
            float4 xv = xr[i], z = wz[i];
            float4 qv;
            qv.x = __fadd_rn(xv.x, __fsub_rn(z.x, xv.x));
            qv.y = __fadd_rn(xv.y, __fsub_rn(z.y, xv.y));
            qv.z = __fadd_rn(xv.z, __fsub_rn(z.z, xv.z));
            qv.w = __fadd_rn(xv.w, __fsub_rn(z.w, xv.w));
            oq[i] = qv;
            float d0 = __fsub_rn(qv.x, xv.x), d1 = __fsub_rn(qv.y, xv.y);
            float d2 = __fsub_rn(qv.z, xv.z), d3 = __fsub_rn(qv.w, xv.w);
            lsum += d0 * d0 + d1 * d1 + d2 * d2 + d3 * d3;
        }
#pragma unroll
        for (int o = 16; o > 0; o >>= 1)
            lsum += __shfl_down_sync(0xffffffffu, lsum, o);
        if ((tid & 31) == 0) wsum[wid] = lsum;
    }
    __syncthreads();
    if (tid == 0) {
        float s = 0.f;
#pragma unroll
        for (int i = 0; i < 8; i++) s += wsum[i];
        atomicAdd(&g_loss, s);
    }
}

// ---------------------------------------------------------------------------
// finalize: loss mean + perplexity
// ---------------------------------------------------------------------------
__global__ void finalize_kernel(float* __restrict__ out) {
    int t = threadIdx.x;
    float s = 0.f;
    for (int i = t; i < M_CB; i += 256) {
        float p = (float)g_counts[i] * (1.0f / 65536.0f);
        s += p * logf(p + 1e-10f);
    }
#pragma unroll
    for (int o = 16; o > 0; o >>= 1)
        s += __shfl_down_sync(0xffffffffu, s, o);
    __shared__ float ws[8];
    if ((t & 31) == 0) ws[t >> 5] = s;
    __syncthreads();
    if (t == 0) {
        float tot = 0.f;
#pragma unroll
        for (int i = 0; i < 8; i++) tot += ws[i];
        out[LOSS_OFF] = g_loss * (1.0f / 8388608.0f);
        out[PERP_OFF] = expf(-tot);
    }
}

// ---------------------------------------------------------------------------
extern "C" void kernel_launch(void* const* d_in, const int* in_sizes, int n_in,
                              void* d_out, int out_size) {
    const float* x = (const float*)d_in[0];
    const float* w = (const float*)d_in[1];
    if (n_in >= 2 && in_sizes[0] == M_CB * D_DIM && in_sizes[1] == Q_ELEMS) {
        x = (const float*)d_in[1];
        w = (const float*)d_in[0];
    }
    float* out = (float*)d_out;

    cudaFuncSetAttribute(vq_main_kernel,
                         cudaFuncAttributeMaxDynamicSharedMemorySize, SM_TOTAL);

    prep_kernel<<<32, 256>>>(w);
    vq_main_kernel<<<BN_TOTAL / 128, 256, SM_TOTAL>>>(x, w, out);
    finalize_kernel<<<1, 256>>>(out);
}

// round 5
// speedup vs baseline: 2.0244x; 1.0167x over previous
#include <cuda_runtime.h>
#include <cuda_bf16.h>
#include <cstdint>

// VQ: B=16, N=4096, D=128, M=2048
// out layout (float32): quantized_st[8388608], loss[1], perp[1], indices[65536]

#define BN_TOTAL 65536
#define M_CB     2048
#define D_DIM    128
#define Q_ELEMS  8388608
#define LOSS_OFF 8388608
#define PERP_OFF 8388609
#define IDX_OFF  8388610

#define ROW_PITCH   272u                 // 136 bf16 per row (128 data + 8 pad)
#define SPLIT_BYTES (M_CB * ROW_PITCH)   // 557056 per split image
#define A_SPLIT     34816u               // 128 rows * 272
#define B_SPLIT     17408u               // 64 rows * 272
#define B_BUF       52224u               // 3 splits
#define N_TILE      64
#define NUM_NT      32

// SMEM map (bytes)
#define SM_A     0u
#define SM_B     104448u                 // 2 bufs * 52224
#define SM_L2K   208896u
#define SM_L2Q   217088u
#define SM_REDV  217600u                 // 128 rows * 4 warps * 4B
#define SM_REDI  219648u
#define SM_BEST  221696u
#define SM_WSUM  222208u                 // 16 warps
#define SM_TOTAL 222272u

__device__ float g_l2k[M_CB];
__device__ int   g_counts[M_CB];
__device__ float g_loss;
__device__ __align__(256) unsigned char g_wsplit[3u * SPLIT_BYTES];

// ---------------------------------------------------------------------------
__device__ __forceinline__ uint32_t smem_to_u32(const void* p) {
    uint32_t a;
    asm("{ .reg .u64 t; cvta.to.shared.u64 t, %1; cvt.u32.u64 %0, t; }"
        : "=r"(a) : "l"(p));
    return a;
}
__device__ __forceinline__ void cp16(uint32_t dst, const void* src) {
    asm volatile("cp.async.cg.shared.global [%0], [%1], 16;"
                 :: "r"(dst), "l"(src) : "memory");
}
__device__ __forceinline__ void cp_commit() {
    asm volatile("cp.async.commit_group;" ::: "memory");
}
__device__ __forceinline__ void cp_wait1() {
    asm volatile("cp.async.wait_group 1;" ::: "memory");
}
__device__ __forceinline__ void cp_wait0() {
    asm volatile("cp.async.wait_group 0;" ::: "memory");
}
__device__ __forceinline__ void ldsm4(uint32_t* r, uint32_t addr) {
    asm volatile("ldmatrix.sync.aligned.m8n8.x4.shared.b16 {%0,%1,%2,%3}, [%4];"
                 : "=r"(r[0]), "=r"(r[1]), "=r"(r[2]), "=r"(r[3]) : "r"(addr));
}
__device__ __forceinline__ void mma_bf16(float* d, const uint32_t* a, const uint32_t* b) {
    asm volatile(
        "mma.sync.aligned.m16n8k16.row.col.f32.bf16.bf16.f32 "
        "{%0,%1,%2,%3}, {%4,%5,%6,%7}, {%8,%9}, {%0,%1,%2,%3};"
        : "+f"(d[0]), "+f"(d[1]), "+f"(d[2]), "+f"(d[3])
        : "r"(a[0]), "r"(a[1]), "r"(a[2]), "r"(a[3]), "r"(b[0]), "r"(b[1]));
}
__device__ __forceinline__ void split3(float v, __nv_bfloat16& h,
                                       __nv_bfloat16& m, __nv_bfloat16& lo) {
    h = __float2bfloat16_rn(v);
    float r1 = __fsub_rn(v, __bfloat162float(h));
    m = __float2bfloat16_rn(r1);
    float r2 = __fsub_rn(r1, __bfloat162float(m));
    lo = __float2bfloat16_rn(r2);
}

// ---------------------------------------------------------------------------
// prep: codebook 3-way bf16 splits into padded gmem images + ||k||^2 + zeroing
// ---------------------------------------------------------------------------
__global__ void prep_kernel(const float* __restrict__ w) {
    const int gt = blockIdx.x * 256 + threadIdx.x;    // 0..8191
#pragma unroll
    for (int i = 0; i < 4; i++) {
        int oct = gt * 4 + i;                         // 0..32767
        int n = oct >> 4, k0 = (oct & 15) << 3;
        const float* src = w + (size_t)n * D_DIM + k0;
        __align__(16) __nv_bfloat16 hi[8], mi[8], lo[8];
#pragma unroll
        for (int j = 0; j < 8; j++) split3(src[j], hi[j], mi[j], lo[j]);
        uint32_t off = (uint32_t)n * ROW_PITCH + (uint32_t)k0 * 2;
        *(uint4*)(g_wsplit + off)                    = *(uint4*)hi;
        *(uint4*)(g_wsplit + SPLIT_BYTES + off)      = *(uint4*)mi;
        *(uint4*)(g_wsplit + 2u * SPLIT_BYTES + off) = *(uint4*)lo;
    }
    if (gt < M_CB) {
        const float* wr = w + (size_t)gt * D_DIM;
        float s = 0.f;
        for (int i = 0; i < D_DIM; i++)
            s = __fadd_rn(s, __fmul_rn(wr[i], wr[i]));   // strict sequential
        g_l2k[gt]    = s;
        g_counts[gt] = 0;
        if (gt == 0) g_loss = 0.f;
    }
}

// ---------------------------------------------------------------------------
__device__ __forceinline__ void load_b(uint32_t sb, int buf, int nt, int tid) {
#pragma unroll
    for (int s = 0; s < 3; s++) {
        const unsigned char* src =
            g_wsplit + (size_t)s * SPLIT_BYTES + (size_t)nt * B_SPLIT;
        uint32_t dst = sb + SM_B + (uint32_t)buf * B_BUF + (uint32_t)s * B_SPLIT;
        for (int i = tid; i < (int)(B_SPLIT / 16); i += 512)
            cp16(dst + (uint32_t)i * 16u, src + (size_t)i * 16);
    }
}

// ---------------------------------------------------------------------------
// main: M=128 query tile per CTA, 512 threads (16 warps, 4x4 warp grid);
// 6-pass split-bf16 HMMA distance GEMM via ldmatrix frags, fused argmin;
// gather/quantized_st/loss/hist epilogue.
// ---------------------------------------------------------------------------
__global__ __launch_bounds__(512, 1)
void vq_main_kernel(const float* __restrict__ x, const float* __restrict__ w,
                    float* __restrict__ out)
{
    extern __shared__ char smem[];
    const uint32_t sb = smem_to_u32(smem);
    const int tid = threadIdx.x;
    const int wid = tid >> 5, l = tid & 31;
    const int wx = wid & 3, wy = wid >> 2;        // wx: M (4), wy: N (4)
    const int lq = l >> 2, lr = l & 3;
    const int m0 = blockIdx.x * 128;

    float* l2k_s  = (float*)(smem + SM_L2K);
    float* l2q_s  = (float*)(smem + SM_L2Q);
    float* redv   = (float*)(smem + SM_REDV);
    int*   redi   = (int*)  (smem + SM_REDI);
    int*   best_s = (int*)  (smem + SM_BEST);
    float* wsum   = (float*)(smem + SM_WSUM);

    // ---- build A split images (hi/mid/lo), padded rows
#pragma unroll
    for (int i = 0; i < 4; i++) {
        int idx = tid + (i << 9);               // 0..2047 octets
        int r = idx >> 4, k0 = (idx & 15) << 3;
        const float4* src = (const float4*)(x + (size_t)(m0 + r) * D_DIM + k0);
        float4 v0 = src[0], v1 = src[1];
        float vv[8] = {v0.x, v0.y, v0.z, v0.w, v1.x, v1.y, v1.z, v1.w};
        __align__(16) __nv_bfloat16 hi[8], mi[8], lo[8];
#pragma unroll
        for (int j = 0; j < 8; j++) split3(vv[j], hi[j], mi[j], lo[j]);
        uint32_t off = SM_A + (uint32_t)r * ROW_PITCH + (uint32_t)k0 * 2;
        *(uint4*)(smem + off)                = *(uint4*)hi;
        *(uint4*)(smem + off + A_SPLIT)      = *(uint4*)mi;
        *(uint4*)(smem + off + 2u * A_SPLIT) = *(uint4*)lo;
    }
    // ---- stage l2k
    if (tid < 256) {
        const float4* src = (const float4*)g_l2k;
        float4* dst = (float4*)l2k_s;
        dst[tid]       = src[tid];
        dst[tid + 256] = src[tid + 256];
    }
    // ---- l2q per row: strict sequential fp32 (reference rounding)
    if (tid < 128) {
        const float* xr = x + (size_t)(m0 + tid) * D_DIM;
        float s = 0.f;
        for (int k = 0; k < D_DIM; k++)
            s = __fadd_rn(s, __fmul_rn(xr[k], xr[k]));
        l2q_s[tid] = s;
    }

    load_b(sb, 0, 0, tid);
    cp_commit();
    __syncthreads();

    float lqr[2][2];
#pragma unroll
    for (int mi = 0; mi < 2; mi++)
#pragma unroll
        for (int h = 0; h < 2; h++)
            lqr[mi][h] = l2q_s[wx * 32 + mi * 16 + h * 8 + lq];

    // ldmatrix lane-address bases
    // A (x4): row = wx*32 + mi*16 + (l&7) + ((l>>3)&1)*8 ; kbyte = ((l>>4)&1)*16
    uint32_t aAddr[3][2];
    {
        uint32_t row = (uint32_t)(wx * 32) + (uint32_t)(l & 7) + (uint32_t)((l >> 3) & 1) * 8u;
        uint32_t kb  = (uint32_t)((l >> 4) & 1) * 16u;
#pragma unroll
        for (int s = 0; s < 3; s++)
#pragma unroll
            for (int mi = 0; mi < 2; mi++)
                aAddr[s][mi] = sb + SM_A + (uint32_t)s * A_SPLIT
                             + (row + (uint32_t)mi * 16u) * ROW_PITCH + kb;
    }
    // B (x4): row = wy*16 + (l&7) + ((l>>4)&1)*8 ; kbyte = ((l>>3)&1)*16
    uint32_t bAddr[3];
    {
        uint32_t row = (uint32_t)(wy * 16) + (uint32_t)(l & 7) + (uint32_t)((l >> 4) & 1) * 8u;
        uint32_t kb  = (uint32_t)((l >> 3) & 1) * 16u;
#pragma unroll
        for (int s = 0; s < 3; s++)
            bAddr[s] = sb + SM_B + (uint32_t)s * B_SPLIT + row * ROW_PITCH + kb;
    }

    float rmin[2][2];
    int   ridx[2][2];
#pragma unroll
    for (int mi = 0; mi < 2; mi++)
#pragma unroll
        for (int h = 0; h < 2; h++) { rmin[mi][h] = 3.0e38f; ridx[mi][h] = 0; }

    for (int nt = 0; nt < NUM_NT; nt++) {
        if (nt + 1 < NUM_NT) {
            load_b(sb, (nt + 1) & 1, nt + 1, tid);
            cp_commit();
            cp_wait1();          // tile nt complete (FIFO)
        } else {
            cp_wait0();
        }
        __syncthreads();

        float acc[2][2][4];
#pragma unroll
        for (int mi = 0; mi < 2; mi++)
#pragma unroll
            for (int ni = 0; ni < 2; ni++)
#pragma unroll
                for (int q = 0; q < 4; q++) acc[mi][ni][q] = 0.f;

        const uint32_t bOff = (uint32_t)(nt & 1) * B_BUF;

#pragma unroll
        for (int c = 0; c < 8; c++) {
            const uint32_t kb = (uint32_t)c * 32u;
            uint32_t aF[3][2][4];
#pragma unroll
            for (int s = 0; s < 3; s++)
#pragma unroll
                for (int mi = 0; mi < 2; mi++)
                    ldsm4(aF[s][mi], aAddr[s][mi] + kb);
            uint32_t bF[3][4];
#pragma unroll
            for (int s = 0; s < 3; s++)
                ldsm4(bF[s], bAddr[s] + bOff + kb);

            const int PA[6] = {0, 0, 1, 0, 2, 1};
            const int PB[6] = {0, 1, 0, 2, 0, 1};
#pragma unroll
            for (int p = 0; p < 6; p++)
#pragma unroll
                for (int mi = 0; mi < 2; mi++)
#pragma unroll
                    for (int ni = 0; ni < 2; ni++)
                        mma_bf16(acc[mi][ni], aF[PA[p]][mi], &bF[PB[p]][ni * 2]);
        }

        // fused argmin epilogue (reference rounding; ascending index order)
#pragma unroll
        for (int mi = 0; mi < 2; mi++)
#pragma unroll
            for (int ni = 0; ni < 2; ni++) {
                const int col0 = nt * 64 + wy * 16 + ni * 8 + (lr << 1);
                const float2 lk = *(const float2*)(l2k_s + col0);
                float v;
                v = __fmaf_rn(-2.f, acc[mi][ni][0], __fadd_rn(lqr[mi][0], lk.x));
                if (v < rmin[mi][0]) { rmin[mi][0] = v; ridx[mi][0] = col0; }
                v = __fmaf_rn(-2.f, acc[mi][ni][1], __fadd_rn(lqr[mi][0], lk.y));
                if (v < rmin[mi][0]) { rmin[mi][0] = v; ridx[mi][0] = col0 + 1; }
                v = __fmaf_rn(-2.f, acc[mi][ni][2], __fadd_rn(lqr[mi][1], lk.x));
                if (v < rmin[mi][1]) { rmin[mi][1] = v; ridx[mi][1] = col0; }
                v = __fmaf_rn(-2.f, acc[mi][ni][3], __fadd_rn(lqr[mi][1], lk.y));
                if (v < rmin[mi][1]) { rmin[mi][1] = v; ridx[mi][1] = col0 + 1; }
            }
        __syncthreads();   // compute done before next iter overwrites this buf
    }

    // ---- cross-lane (4 lanes share a row) then cross-warp (4 wy) reduction
#pragma unroll
    for (int mi = 0; mi < 2; mi++)
#pragma unroll
        for (int h = 0; h < 2; h++) {
            float v = rmin[mi][h];
            int   ix = ridx[mi][h];
#pragma unroll
            for (int off = 1; off <= 2; off <<= 1) {
                float ov = __shfl_xor_sync(0xffffffffu, v, off);
                int   oi = __shfl_xor_sync(0xffffffffu, ix, off);
                if (ov < v || (ov == v && oi < ix)) { v = ov; ix = oi; }
            }
            if (lr == 0) {
                int row = wx * 32 + mi * 16 + h * 8 + lq;
                redv[row * 4 + wy] = v;
                redi[row * 4 + wy] = ix;
            }
        }
    __syncthreads();
    if (tid < 128) {
        float bv = redv[tid * 4]; int bi = redi[tid * 4];
#pragma unroll
        for (int j = 1; j < 4; j++) {
            float v = redv[tid * 4 + j]; int ix = redi[tid * 4 + j];
            if (v < bv || (v == bv && ix < bi)) { bv = v; bi = ix; }
        }
        best_s[tid] = bi;
        atomicAdd(&g_counts[bi], 1);
        out[IDX_OFF + m0 + tid] = (float)bi;
    }
    __syncthreads();

    // ---- gather z, quantized_st = x + (z - x), loss partial (quarter-row/thread)
    {
        const int r  = tid >> 2;
        const int kb = (tid & 3) << 5;
        const int best = best_s[r];
        const float4* xr = (const float4*)(x + (size_t)(m0 + r) * D_DIM + kb);
        const float4* wz = (const float4*)(w + (size_t)best * D_DIM + kb);
        float4* oq = (float4*)(out + (size_t)(m0 + r) * D_DIM + kb);
        float lsum = 0.f;
#pragma unroll
        for (int i = 0; i < 8; i++) {
            float4 xv = xr[i], z = wz[i];
            float4 qv;
            qv.x = __fadd_rn(xv.x, __fsub_rn(z.x, xv.x));
            qv.y = __fadd_rn(xv.y, __fsub_rn(z.y, xv.y));
            qv.z = __fadd_rn(xv.z, __fsub_rn(z.z, xv.z));
            qv.w = __fadd_rn(xv.w, __fsub_rn(z.w, xv.w));
            oq[i] = qv;
            float d0 = __fsub_rn(qv.x, xv.x), d1 = __fsub_rn(qv.y, xv.y);
            float d2 = __fsub_rn(qv.z, xv.z), d3 = __fsub_rn(qv.w, xv.w);
            lsum += d0 * d0 + d1 * d1 + d2 * d2 + d3 * d3;
        }
#pragma unroll
        for (int o = 16; o > 0; o >>= 1)
            lsum += __shfl_down_sync(0xffffffffu, lsum, o);
        if ((tid & 31) == 0) wsum[wid] = lsum;
    }
    __syncthreads();
    if (tid == 0) {
        float s = 0.f;
#pragma unroll
        for (int i = 0; i < 16; i++) s += wsum[i];
        atomicAdd(&g_loss, s);
    }
}

// ---------------------------------------------------------------------------
// finalize: loss mean + perplexity
// ---------------------------------------------------------------------------
__global__ void finalize_kernel(float* __restrict__ out) {
    int t = threadIdx.x;
    float s = 0.f;
    for (int i = t; i < M_CB; i += 256) {
        float p = (float)g_counts[i] * (1.0f / 65536.0f);
        s += p * logf(p + 1e-10f);
    }
#pragma unroll
    for (int o = 16; o > 0; o >>= 1)
        s += __shfl_down_sync(0xffffffffu, s, o);
    __shared__ float ws[8];
    if ((t & 31) == 0) ws[t >> 5] = s;
    __syncthreads();
    if (t == 0) {
        float tot = 0.f;
#pragma unroll
        for (int i = 0; i < 8; i++) tot += ws[i];
        out[LOSS_OFF] = g_loss * (1.0f / 8388608.0f);
        out[PERP_OFF] = expf(-tot);
    }
}

// ---------------------------------------------------------------------------
extern "C" void kernel_launch(void* const* d_in, const int* in_sizes, int n_in,
                              void* d_out, int out_size) {
    const float* x = (const float*)d_in[0];
    const float* w = (const float*)d_in[1];
    if (n_in >= 2 && in_sizes[0] == M_CB * D_DIM && in_sizes[1] == Q_ELEMS) {
        x = (const float*)d_in[1];
        w = (const float*)d_in[0];
    }
    float* out = (float*)d_out;

    cudaFuncSetAttribute(vq_main_kernel,
                         cudaFuncAttributeMaxDynamicSharedMemorySize, SM_TOTAL);

    prep_kernel<<<32, 256>>>(w);
    vq_main_kernel<<<BN_TOTAL / 128, 512, SM_TOTAL>>>(x, w, out);
    finalize_kernel<<<1, 256>>>(out);
}